// round 9
// baseline (speedup 1.0000x reference)
#include <cuda_runtime.h>
#include <cuda_fp16.h>
#include <math_constants.h>
#include <cstdint>

#define NROWS 16384
#define DIM   256
#define KCB   8192
#define MT    64                 /* rows per CTA           */
#define MTILES (NROWS / MT)      /* 256 CTAs               */
#define NTILES (KCB / 128)       /* 64 code tiles          */
#define NHALF  (2 * NTILES)      /* 128 k128xn128 halves   */
#define NPART (NROWS / 8)

/* GEMM smem layout (dynamic) */
#define SA_OFF  0                /* A fp16: 64 rows x 512B = 32KB      */
#define SB_OFF  32768            /* 2 x 32KB B half double buffer      */
#define SCN_OFF 98304            /* 2 x 512B codenorm tiles            */
#define GEMM_SMEM 99328

/* ------------- device globals (no allocs allowed) ------------- */
__device__ unsigned char g_zt[MTILES * 32768];       /* 8MB pre-swizzled A fp16 (row=512B)      */
__device__ unsigned char g_cbt[NHALF * 32768];       /* 4MB pre-swizzled B fp16 n-major halves  */
__device__ float g_codenorm[KCB];
__device__ int   g_cand[NROWS * 4];
__device__ float g_losspart[NPART];
__device__ unsigned g_ctr;

/* ------------- helpers ------------- */
__device__ __forceinline__ unsigned smem_u32(const void* p) {
    unsigned a;
    asm("{ .reg .u64 t; cvta.to.shared.u64 t, %1; cvt.u32.u64 %0, t; }" : "=r"(a) : "l"(p));
    return a;
}
__device__ __forceinline__ void cp_async16(unsigned dst, const void* src) {
    asm volatile("cp.async.cg.shared.global [%0], [%1], 16;" :: "r"(dst), "l"(src) : "memory");
}
__device__ __forceinline__ void ldsm_x4(unsigned* r, unsigned addr) {
    asm("ldmatrix.sync.aligned.m8n8.x4.shared.b16 {%0,%1,%2,%3}, [%4];"
        : "=r"(r[0]), "=r"(r[1]), "=r"(r[2]), "=r"(r[3]) : "r"(addr));
}
__device__ __forceinline__ void mma16816(float (&c)[4], const unsigned* a, unsigned b0, unsigned b1) {
    asm volatile("mma.sync.aligned.m16n8k16.row.col.f32.f16.f16.f32 "
                 "{%0,%1,%2,%3}, {%4,%5,%6,%7}, {%8,%9}, {%0,%1,%2,%3};"
                 : "+f"(c[0]), "+f"(c[1]), "+f"(c[2]), "+f"(c[3])
                 : "r"(a[0]), "r"(a[1]), "r"(a[2]), "r"(a[3]), "r"(b0), "r"(b1));
}
__device__ __forceinline__ void top2_update(float& v1, int& i1, float& v2, int& i2, float d, int c) {
    if (d < v2) {
        if (d < v1) { v2 = v1; i2 = i1; v1 = d; i1 = c; }
        else        { v2 = d;  i2 = c; }
    }
}
__device__ __forceinline__ void ins4(float (&cv)[4], int (&ci)[4], float v, int i) {
#pragma unroll
    for (int j = 0; j < 4; j++) {
        bool lt = (v < cv[j]) || (v == cv[j] && i < ci[j]);
        float tv = lt ? cv[j] : v; int ti = lt ? ci[j] : i;
        if (lt) { cv[j] = v; ci[j] = i; }
        v = tv; i = ti;
    }
}

/* ---------- preprocess: z -> swizzled fp16 tiles (64 rows x 512B, full k) ---------- */
__global__ void split_z_kernel(const float* __restrict__ z) {
    const int id = blockIdx.x * 256 + threadIdx.x;   /* 0..524287 */
    const int row = id >> 5;
    const int j = id & 31;                           /* 16B chunk (8 fp16) along k */
    const float* src = z + (size_t)row * DIM + j * 8;
    float4 f0 = __ldg((const float4*)src);
    float4 f1 = __ldg((const float4*)(src + 4));
    float v[8] = {f0.x, f0.y, f0.z, f0.w, f1.x, f1.y, f1.z, f1.w};
    unsigned short hv[8];
#pragma unroll
    for (int e = 0; e < 8; e++) hv[e] = __half_as_ushort(__float2half_rn(v[e]));
    size_t base = (size_t)(row >> 6) * 32768 + (size_t)(row & 63) * 512 + ((j ^ (row & 7)) << 4);
    *(uint4*)(g_zt + base) = *(uint4*)hv;
}

/* ---------- preprocess: codebook -> n-major swizzled fp16 halves (128n x 256B) ---------- */
__global__ void split_cb_kernel(const float* __restrict__ cb) {
    const int id = blockIdx.x * 256 + threadIdx.x;   /* 0..262143 */
    const int n = id >> 5;                           /* code row 0..8191 */
    const int j = id & 31;                           /* 16B chunk over full k256 */
    const float* src = cb + (size_t)n * DIM + j * 8;
    float4 f0 = __ldg((const float4*)src);
    float4 f1 = __ldg((const float4*)(src + 4));
    float v[8] = {f0.x, f0.y, f0.z, f0.w, f1.x, f1.y, f1.z, f1.w};
    unsigned short hv[8];
#pragma unroll
    for (int e = 0; e < 8; e++) hv[e] = __half_as_ushort(__float2half_rn(v[e]));
    const int h = j >> 4, kb = j & 15;               /* k-half, chunk within half */
    const int nt = n >> 7, nr = n & 127;
    size_t base = ((size_t)nt * 2 + h) * 32768 + (size_t)nr * 256 + ((kb ^ (nr & 7)) << 4);
    *(uint4*)(g_cbt + base) = *(uint4*)hv;
}

/* ---------- exact fp32 codebook norms ---------- */
__global__ void codenorm_kernel(const float* __restrict__ cb) {
    int warp = threadIdx.x >> 5, lane = threadIdx.x & 31;
    int row = blockIdx.x * 8 + warp;
    const float4* c4 = (const float4*)(cb + (size_t)row * DIM);
    float s = 0.f;
#pragma unroll
    for (int l = 0; l < 2; l++) {
        float4 v = c4[lane + 32 * l];
        s += v.x * v.x + v.y * v.y + v.z * v.z + v.w * v.w;
    }
#pragma unroll
    for (int o = 16; o > 0; o >>= 1) s += __shfl_down_sync(0xffffffffu, s, o);
    if (lane == 0) g_codenorm[row] = s;
}

/* ---------- B-half producer: 32KB into buffer (s&1), one commit group (128 thr) ---------- */
__device__ __forceinline__ void issue_half(unsigned smb, int s, int tid) {
    const unsigned char* src = g_cbt + (size_t)s * 32768 + tid * 16;
    unsigned dst = smb + SB_OFF + (s & 1) * 32768 + tid * 16;
#pragma unroll
    for (int i = 0; i < 16; i++) cp_async16(dst + i * 2048, src + (size_t)i * 2048);
    if ((s & 1) == 0 && tid < 32)
        cp_async16(smb + SCN_OFF + ((s >> 1) & 1) * 512 + tid * 16,
                   (const unsigned char*)g_codenorm + (size_t)(s >> 1) * 512 + tid * 16);
    asm volatile("cp.async.commit_group;" ::: "memory");
}

/* ---------- compute one k128 half: 8 k16-steps, warp tile 64m x 32n, buf = H ---------- */
template<int H>
__device__ __forceinline__ void compute_half(float (&acc)[4][4][4], unsigned smb,
                                             int wn, int lane) {
    const int lm = lane & 15;
    const int sel = lane >> 4;
    const int xa = lm & 7;
    unsigned abase[4];
#pragma unroll
    for (int mi = 0; mi < 4; mi++)
        abase[mi] = smb + SA_OFF + (mi * 16 + lm) * 512 + H * 256;
    const unsigned bb = smb + SB_OFF + H * 32768 + (wn * 32 + lm) * 256;
    unsigned bbase[2] = {bb, bb + 16 * 256};
#pragma unroll
    for (int ks = 0; ks < 8; ks++) {
        const unsigned off = (unsigned)(((ks * 2 + sel) ^ xa) << 4);
        unsigned a[4][4], b[2][4];
#pragma unroll
        for (int mi = 0; mi < 4; mi++) ldsm_x4(a[mi], abase[mi] + off);
        ldsm_x4(b[0], bbase[0] + off);
        ldsm_x4(b[1], bbase[1] + off);
#pragma unroll
        for (int mi = 0; mi < 4; mi++) {
            mma16816(acc[mi][0], a[mi], b[0][0], b[0][2]);
            mma16816(acc[mi][1], a[mi], b[0][1], b[0][3]);
            mma16816(acc[mi][2], a[mi], b[1][0], b[1][2]);
            mma16816(acc[mi][3], a[mi], b[1][1], b[1][3]);
        }
    }
}

/* ---------- K1: fp16 tensor GEMM + fused top-2/thread argmin (128 threads) ---------- */
__global__ void __launch_bounds__(128, 2) vq_mma_kernel() {
    extern __shared__ __align__(128) unsigned char smem[];
    const unsigned smb = smem_u32(smem);
    const int tid = threadIdx.x;
    const int lane = tid & 31;
    const int wn = tid >> 5;                 /* 4 warps, each owns 32 n-cols */
    const int mtile = blockIdx.x;

    if (mtile == 0 && tid == 0) g_ctr = 0;

    { /* prologue group: resident A (32KB) + half 0 + cn tile 0 */
        const unsigned char* src = g_zt + (size_t)mtile * 32768 + tid * 16;
        unsigned dst = smb + SA_OFF + tid * 16;
#pragma unroll
        for (int i = 0; i < 16; i++) cp_async16(dst + i * 2048, src + (size_t)i * 2048);
        issue_half(smb, 0, tid);
    }

    float acc[4][4][4];
#pragma unroll
    for (int i = 0; i < 4; i++)
#pragma unroll
        for (int j = 0; j < 4; j++)
#pragma unroll
            for (int r = 0; r < 4; r++) acc[i][j][r] = 0.f;
    float tv1[8], tv2[8];
    int ti1[8], ti2[8];
#pragma unroll
    for (int sl = 0; sl < 8; sl++) { tv1[sl] = CUDART_INF_F; tv2[sl] = CUDART_INF_F; ti1[sl] = 0; ti2[sl] = 0; }

    const int colb = wn * 32 + 2 * (lane & 3);
    for (int ii = 0; ii < NTILES; ii++) {
        /* ---- half 0 of tile ii ---- */
        asm volatile("cp.async.wait_group 0;" ::: "memory");
        __syncthreads();
        issue_half(smb, 2 * ii + 1, tid);
        compute_half<0>(acc, smb, wn, lane);
        /* ---- half 1 of tile ii ---- */
        asm volatile("cp.async.wait_group 0;" ::: "memory");
        __syncthreads();
        if (2 * ii + 2 < NHALF) issue_half(smb, 2 * ii + 2, tid);
        compute_half<1>(acc, smb, wn, lane);
        { /* epilogue: dist + top-2, zero acc */
            const float* cnp = (const float*)(smem + SCN_OFF + (ii & 1) * 512);
#pragma unroll
            for (int ni = 0; ni < 4; ni++) {
                float cn0 = cnp[colb + ni * 8];
                float cn1 = cnp[colb + ni * 8 + 1];
                int c0 = ii * 128 + colb + ni * 8;
#pragma unroll
                for (int mi = 0; mi < 4; mi++) {
#pragma unroll
                    for (int h = 0; h < 2; h++) {
                        int sl = mi * 2 + h;
                        float d0 = fmaf(-2.f, acc[mi][ni][h * 2],     cn0);
                        float d1 = fmaf(-2.f, acc[mi][ni][h * 2 + 1], cn1);
                        top2_update(tv1[sl], ti1[sl], tv2[sl], ti2[sl], d0, c0);
                        top2_update(tv1[sl], ti1[sl], tv2[sl], ti2[sl], d1, c0 + 1);
                        acc[mi][ni][h * 2] = 0.f;
                        acc[mi][ni][h * 2 + 1] = 0.f;
                    }
                }
            }
        }
    }

    /* dump all 32 per-row candidates, then per-row top-4 merge */
    __syncthreads();
    float4* red = (float4*)(smem + SB_OFF);    /* 64 rows x 16 entries x 16B */
#pragma unroll
    for (int sl = 0; sl < 8; sl++) {
        int row = (sl >> 1) * 16 + (sl & 1) * 8 + (lane >> 2);
        red[row * 16 + wn * 4 + (lane & 3)] =
            make_float4(tv1[sl], __int_as_float(ti1[sl]), tv2[sl], __int_as_float(ti2[sl]));
    }
    __syncthreads();
    if (tid < 64) {
        float cv[4] = {CUDART_INF_F, CUDART_INF_F, CUDART_INF_F, CUDART_INF_F};
        int ci[4] = {0x7fffffff, 0x7fffffff, 0x7fffffff, 0x7fffffff};
#pragma unroll
        for (int e = 0; e < 16; e++) {
            float4 f = red[tid * 16 + e];
            ins4(cv, ci, f.x, __float_as_int(f.y));
            ins4(cv, ci, f.z, __float_as_int(f.w));
        }
        *(int4*)(g_cand + (size_t)(mtile * MT + tid) * 4) = make_int4(ci[0], ci[1], ci[2], ci[3]);
    }
}

/* ---------- K2: exact fp32 rescore of top-4 + gather + loss (last block finalizes) ---------- */
__global__ void rescore_gather_kernel(const float* __restrict__ z,
                                      const float* __restrict__ cb,
                                      float* __restrict__ out) {
    const int lane = threadIdx.x & 31, warp = threadIdx.x >> 5;
    const int row = blockIdx.x * 8 + warp;
    __shared__ float wsum[8];
    __shared__ float sred[256];
    __shared__ int s_last;

    const int4 cc = *(const int4*)(g_cand + (size_t)row * 4);
    const int cand[4] = {cc.x, cc.y, cc.z, cc.w};
    const float4* z4 = (const float4*)(z + (size_t)row * DIM);
    float4 a[2], b[4][2];
    float d[4] = {0.f, 0.f, 0.f, 0.f};
#pragma unroll
    for (int l = 0; l < 2; l++) {
        int f = lane + 32 * l;
        a[l] = z4[f];
#pragma unroll
        for (int q = 0; q < 4; q++) {
            b[q][l] = ((const float4*)(cb + (size_t)cand[q] * DIM))[f];
            d[q] += a[l].x * b[q][l].x + a[l].y * b[q][l].y
                  + a[l].z * b[q][l].z + a[l].w * b[q][l].w;
        }
    }
#pragma unroll
    for (int o = 16; o > 0; o >>= 1)
#pragma unroll
        for (int q = 0; q < 4; q++) d[q] += __shfl_xor_sync(0xffffffffu, d[q], o);

    float bv = CUDART_INF_F; int bq = 0, bi = 0x7fffffff;
#pragma unroll
    for (int q = 0; q < 4; q++) {
        float dist = fmaf(-2.f, d[q], __ldg(&g_codenorm[cand[q]]));
        if (dist < bv || (dist == bv && cand[q] < bi)) { bv = dist; bi = cand[q]; bq = q; }
    }

    float* out_ze = out + (size_t)row * DIM;
    float* out_zq = out + (size_t)NROWS * DIM + 1 + (size_t)row * DIM;
    float s = 0.f;
#pragma unroll
    for (int l = 0; l < 2; l++) {
        int f = lane + 32 * l;
        float4 ze = a[l];
        float4 zq = b[bq][l];
        *(float4*)(out_ze + f * 4) = ze;
        out_zq[f * 4 + 0] = zq.x; out_zq[f * 4 + 1] = zq.y;
        out_zq[f * 4 + 2] = zq.z; out_zq[f * 4 + 3] = zq.w;
        float dx = zq.x - ze.x, dy = zq.y - ze.y, dz = zq.z - ze.z, dw = zq.w - ze.w;
        s += dx * dx + dy * dy + dz * dz + dw * dw;
    }
#pragma unroll
    for (int o = 16; o > 0; o >>= 1) s += __shfl_down_sync(0xffffffffu, s, o);
    if (lane == 0) wsum[warp] = s;
    __syncthreads();
    if (threadIdx.x == 0) {
        float t = 0.f;
#pragma unroll
        for (int wv = 0; wv < 8; wv++) t += wsum[wv];
        g_losspart[blockIdx.x] = t;
        __threadfence();
        unsigned r = atomicAdd(&g_ctr, 1u);
        s_last = (r == NPART - 1) ? 1 : 0;
    }
    __syncthreads();
    if (s_last) {  /* last block: deterministic fixed-order final reduce */
        float t = 0.f;
        for (int i = threadIdx.x; i < NPART; i += 256) t += g_losspart[i];
        sred[threadIdx.x] = t;
        __syncthreads();
        for (int o = 128; o > 0; o >>= 1) {
            if (threadIdx.x < o) sred[threadIdx.x] += sred[threadIdx.x + o];
            __syncthreads();
        }
        if (threadIdx.x == 0)
            out[(size_t)NROWS * DIM] = 2.f * sred[0] / (float)((size_t)NROWS * DIM);
    }
}

extern "C" void kernel_launch(void* const* d_in, const int* in_sizes, int n_in,
                              void* d_out, int out_size) {
    const float* z  = (const float*)d_in[0];
    const float* cb = (const float*)d_in[1];
    float* out = (float*)d_out;

    cudaFuncSetAttribute(vq_mma_kernel, cudaFuncAttributeMaxDynamicSharedMemorySize, GEMM_SMEM);

    split_z_kernel<<<NROWS * 32 / 256, 256>>>(z);
    split_cb_kernel<<<KCB * 32 / 256, 256>>>(cb);
    codenorm_kernel<<<KCB / 8, 256>>>(cb);
    vq_mma_kernel<<<MTILES, 128, GEMM_SMEM>>>();
    rescore_gather_kernel<<<NPART, 256>>>(z, cb, out);
}